// round 4
// baseline (speedup 1.0000x reference)
#include <cuda_runtime.h>

#define H    256
#define AH   128
#define NHET 3
#define BSEG 64
#define TM   128
#define KC   16
#define NKC  (H / KC)      // 16

// ---------- batch dtype handling (int32 vs int64, auto-detected) ----------
__device__ __forceinline__ int batch_is64(const void* b, int N) {
    // int64 little-endian: word (N-1) is a high half of one of the first N/2
    // values (all 0..63) -> 0.  int32: word (N-1) = last (max) segment id != 0.
    return ((const int*)b)[N - 1] == 0;
}
__device__ __forceinline__ int bval(const void* b, int i, int is64) {
    return is64 ? (int)((const long long*)b)[i] : ((const int*)b)[i];
}
// first index i with batch[i] >= s   (batch sorted ascending)
__device__ int seg_lower_bound(const void* b, int N, int s, int is64) {
    int lo = 0, hi = N;
    while (lo < hi) {
        int m = (lo + hi) >> 1;
        if (bval(b, m, is64) < s) lo = m + 1; else hi = m;
    }
    return lo;
}

// ---------------- K1: gate GEMM -> e = exp(raw), staged into attn region ----------------
__global__ __launch_bounds__(256)
void gate_kernel(const float* __restrict__ x,
                 const float* __restrict__ het,
                 const float* __restrict__ W1,
                 const float* __restrict__ b1,
                 const float* __restrict__ W2,
                 const float* __restrict__ b2,
                 float* __restrict__ e_out,
                 int N) {
    __shared__ float As[KC][TM];      // k-major A tile
    __shared__ float Bs[KC][AH];      // W1 chunk
    __shared__ float red[16][TM];     // partial raw reduction

    const int tid = threadIdx.x;
    const int tx  = tid & 15;         // output-col group (8 cols)
    const int ty  = tid >> 4;         // node-row group (8 rows)
    const int m0  = blockIdx.x * TM;
    const int r0  = ty * 8;
    const int c0  = tx * 8;

    float acc[8][8];
#pragma unroll
    for (int i = 0; i < 8; ++i)
#pragma unroll
        for (int j = 0; j < 8; ++j) acc[i][j] = 0.0f;

    float4 pa[2], pb[2];

    // prefetch chunk 0.
    // A: 128 rows x 16 floats = 512 float4: row = f4>>2, c4 = f4&3.
    // B: 16 k-rows x 128 cols = 512 float4: krow = f4>>5, bc4 = f4&31.
#pragma unroll
    for (int it = 0; it < 2; ++it) {
        int f4  = it * 256 + tid;
        int row = f4 >> 2, c4 = f4 & 3;
        int g   = m0 + row;
        pa[it] = (g < N) ? *reinterpret_cast<const float4*>(&x[(long)g * H + c4 * 4])
                         : make_float4(0.f, 0.f, 0.f, 0.f);
        int krow = f4 >> 5, bc4 = f4 & 31;
        pb[it] = *reinterpret_cast<const float4*>(&W1[(long)krow * AH + bc4 * 4]);
    }

    for (int c = 0; c < NKC; ++c) {
        __syncthreads();
#pragma unroll
        for (int it = 0; it < 2; ++it) {
            int f4  = it * 256 + tid;
            int row = f4 >> 2, c4 = f4 & 3;
            As[c4 * 4 + 0][row] = pa[it].x;
            As[c4 * 4 + 1][row] = pa[it].y;
            As[c4 * 4 + 2][row] = pa[it].z;
            As[c4 * 4 + 3][row] = pa[it].w;
            int krow = f4 >> 5, bc4 = f4 & 31;
            Bs[krow][bc4 * 4 + 0] = pb[it].x;
            Bs[krow][bc4 * 4 + 1] = pb[it].y;
            Bs[krow][bc4 * 4 + 2] = pb[it].z;
            Bs[krow][bc4 * 4 + 3] = pb[it].w;
        }
        __syncthreads();
        if (c + 1 < NKC) {
            int kb = (c + 1) * KC;
#pragma unroll
            for (int it = 0; it < 2; ++it) {
                int f4  = it * 256 + tid;
                int row = f4 >> 2, c4 = f4 & 3;
                int g   = m0 + row;
                pa[it] = (g < N) ? *reinterpret_cast<const float4*>(&x[(long)g * H + kb + c4 * 4])
                                 : make_float4(0.f, 0.f, 0.f, 0.f);
                int krow = f4 >> 5, bc4 = f4 & 31;
                pb[it] = *reinterpret_cast<const float4*>(&W1[(long)(kb + krow) * AH + bc4 * 4]);
            }
        }
#pragma unroll
        for (int k = 0; k < KC; ++k) {
            float av[8], bw[8];
#pragma unroll
            for (int q = 0; q < 8; ++q) {
                av[q] = As[k][r0 + q];
                bw[q] = Bs[k][c0 + q];
            }
#pragma unroll
            for (int i = 0; i < 8; ++i)
#pragma unroll
                for (int j = 0; j < 8; ++j)
                    acc[i][j] = fmaf(av[i], bw[j], acc[i][j]);
        }
    }

    // epilogue: het columns + bias + tanh + W2 dot, reduce across tx, exp
    __syncthreads();
#pragma unroll
    for (int rr = 0; rr < 8; ++rr) {
        int g = m0 + r0 + rr;
        float s = 0.f;
        if (g < N) {
            float h0 = het[(long)g * NHET + 0];
            float h1 = het[(long)g * NHET + 1];
            float h2 = het[(long)g * NHET + 2];
#pragma unroll
            for (int j = 0; j < 8; ++j) {
                float v = acc[rr][j] + b1[c0 + j]
                        + h0 * W1[(long)(H + 0) * AH + c0 + j]
                        + h1 * W1[(long)(H + 1) * AH + c0 + j]
                        + h2 * W1[(long)(H + 2) * AH + c0 + j];
                s += tanhf(v) * W2[c0 + j];
            }
        }
        red[tx][r0 + rr] = s;
    }
    __syncthreads();

    if (tid < TM && (m0 + tid) < N) {
        float s = 0.f;
#pragma unroll
        for (int t = 0; t < 16; ++t) s += red[t][tid];
        e_out[m0 + tid] = expf(s + b2[0]);
    }
}

// ---------------- K2: S[seg, col] = sum_{i in seg} e_i * x[i, col] ----------------
// grid = 64 segs * 8 col-groups; block = 256 (8 row-lanes x 32 cols)
__global__ __launch_bounds__(256)
void seg_accum_kernel(const float* __restrict__ x,
                      const void* __restrict__ batch,
                      const float* __restrict__ e,
                      float* __restrict__ Sout,
                      int N) {
    __shared__ int range[2];
    __shared__ float sred[8][33];

    const int seg = blockIdx.x >> 3;
    const int cg  = blockIdx.x & 7;
    const int tid = threadIdx.x;
    const int tr  = tid >> 5;       // 0..7
    const int tc  = tid & 31;       // 0..31

    const int is64 = batch_is64(batch, N);
    if (tid == 0) {
        range[0] = seg_lower_bound(batch, N, seg,     is64);
        range[1] = seg_lower_bound(batch, N, seg + 1, is64);
    }
    __syncthreads();
    const int s0 = range[0], e0 = range[1];
    const int col = cg * 32 + tc;

    float a0 = 0.f, a1 = 0.f, a2 = 0.f, a3 = 0.f;
    int i = s0 + tr;
    for (; i + 24 < e0; i += 32) {
        a0 += e[i]      * x[(long)i        * H + col];
        a1 += e[i + 8]  * x[(long)(i + 8)  * H + col];
        a2 += e[i + 16] * x[(long)(i + 16) * H + col];
        a3 += e[i + 24] * x[(long)(i + 24) * H + col];
    }
    for (; i < e0; i += 8)
        a0 += e[i] * x[(long)i * H + col];

    sred[tr][tc] = (a0 + a1) + (a2 + a3);
    __syncthreads();
    if (tr == 0) {
        float s = sred[0][tc];
#pragma unroll
        for (int t = 1; t < 8; ++t) s += sred[t][tc];
        Sout[seg * H + col] = s;
    }
}

// ---------------- K3: denom, z = (S/denom)@Wv + bv, attn = e/denom ----------------
// grid = 64 (one block per segment), block = 256 (= H)
__global__ __launch_bounds__(256)
void finalize_kernel(const void* __restrict__ batch,
                     const float* __restrict__ Wv,
                     const float* __restrict__ bv,
                     float* __restrict__ zreg,   // holds S on entry, z on exit
                     float* __restrict__ attn,   // holds e on entry, attn on exit
                     int N) {
    __shared__ int range[2];
    __shared__ float sb[H];
    __shared__ float rs[256];

    const int b   = blockIdx.x;
    const int tid = threadIdx.x;

    const int is64 = batch_is64(batch, N);
    if (tid == 0) {
        range[0] = seg_lower_bound(batch, N, b,     is64);
        range[1] = seg_lower_bound(batch, N, b + 1, is64);
    }
    __syncthreads();
    const int s0 = range[0], e0 = range[1];

    // denom = sum of e over segment
    float p = 0.f;
    for (int i = s0 + tid; i < e0; i += 256) p += attn[i];
    rs[tid] = p;
    __syncthreads();
    for (int off = 128; off > 0; off >>= 1) {
        if (tid < off) rs[tid] += rs[tid + off];
        __syncthreads();
    }
    const float denom = rs[0];
    const float inv   = (e0 > s0) ? 1.f / denom : 0.f;

    // normalized S row -> shared
    sb[tid] = zreg[b * H + tid] * inv;
    __syncthreads();

    // z row
    float acc = 0.f;
    if (e0 > s0) {
        acc = bv[tid];
#pragma unroll 8
        for (int k = 0; k < H; ++k)
            acc += sb[k] * Wv[(long)k * H + tid];
    }
    zreg[b * H + tid] = acc;

    // attn normalize (disjoint per block)
    for (int i = s0 + tid; i < e0; i += 256) attn[i] *= inv;
}

extern "C" void kernel_launch(void* const* d_in, const int* in_sizes, int n_in,
                              void* d_out, int out_size) {
    const float* x   = (const float*)d_in[0];
    const float* het = (const float*)d_in[1];
    const void*  batch = d_in[2];              // int32 or int64, auto-detected
    const float* W1  = (const float*)d_in[3];
    const float* b1  = (const float*)d_in[4];
    const float* W2  = (const float*)d_in[5];
    const float* b2  = (const float*)d_in[6];
    const float* Wv  = (const float*)d_in[7];
    const float* bv  = (const float*)d_in[8];
    float* out = (float*)d_out;

    const int N = in_sizes[2];                 // batch element count
    float* zreg = out;                         // [BSEG*H]  z (S staged here)
    float* attn = out + BSEG * H;              // [N]       attn (e staged here)

    gate_kernel<<<(N + TM - 1) / TM, 256>>>(x, het, W1, b1, W2, b2, attn, N);
    seg_accum_kernel<<<BSEG * 8, 256>>>(x, batch, attn, zreg, N);
    finalize_kernel<<<BSEG, 256>>>(batch, Wv, bv, zreg, attn, N);
}